// round 1
// baseline (speedup 1.0000x reference)
#include <cuda_runtime.h>
#include <math_constants.h>

#define N_NODES 50000
#define HID     128
#define E_EDGES 640000
#define HEADS   2
#define CPH     64           // channels per head
#define ATT_SLOPE 0.2f
#define OUT_SLOPE 0.01f

// ---------------- scratch (device globals; no allocation allowed) ----------
__device__ float g_xl[N_NODES * HID];
__device__ float g_xr[N_NODES * HID];
__device__ float g_h1[N_NODES * HID];
__device__ float g_acc[N_NODES * HID];
__device__ float g_alpha[E_EDGES * HEADS];
__device__ float g_amax[N_NODES * HEADS];
__device__ float g_asum[N_NODES * HEADS];
__device__ float g_wt[HID * 2 * HID];   // [k][256] : cols 0..127 = W_l, 128..255 = W_r

__device__ __forceinline__ float lrelu(float x, float s) {
    return x > 0.f ? x : s * x;
}

__device__ __forceinline__ void atomicMaxF(float* addr, float v) {
    if (v >= 0.f) {
        atomicMax((int*)addr, __float_as_int(v));
    } else {
        atomicMin((unsigned int*)addr, __float_as_uint(v));
    }
}

// ---------------- W transpose: [o][k] -> [k][o || 128+o] -----------------
__global__ void k_transpose(const float* __restrict__ wl, const float* __restrict__ wr) {
    int i = blockIdx.x * blockDim.x + threadIdx.x;
    if (i < HID * HID) {
        int o = i / HID, k = i % HID;
        g_wt[k * 256 + o]       = wl[i];
        g_wt[k * 256 + 128 + o] = wr[i];
    }
}

// ---------------- fused GEMM: out[n, 0:128]=X*Wl^T -> g_xl, [128:256] -> g_xr
// tile: 64 rows x 256 cols, 256 threads, 8x8 micro-tile per thread, BK=32
#define BM 64
#define BK 32
__global__ void __launch_bounds__(256, 2) k_gemm(const float* __restrict__ X) {
    __shared__ float Xs[BM * BK];
    __shared__ float Ws[BK * 256];
    const int tid  = threadIdx.x;
    const int warp = tid >> 5;      // 0..7 -> row group
    const int lane = tid & 31;      // 0..31 -> col group (8 cols each)
    const int row0 = blockIdx.x * BM;

    float acc[8][8];
#pragma unroll
    for (int i = 0; i < 8; i++)
#pragma unroll
        for (int j = 0; j < 8; j++) acc[i][j] = 0.f;

    for (int k0 = 0; k0 < HID; k0 += BK) {
        // load X tile 64x32 (2048 floats)
#pragma unroll
        for (int t = 0; t < 2; t++) {
            int idx = (tid + t * 256) * 4;
            int r = idx >> 5, kk = idx & 31;
            int rg = row0 + r;
            float4 v = make_float4(0.f, 0.f, 0.f, 0.f);
            if (rg < N_NODES)
                v = *(const float4*)(X + (size_t)rg * HID + k0 + kk);
            *(float4*)(Xs + r * BK + kk) = v;
        }
        // load W tile 32x256 (8192 floats)
#pragma unroll
        for (int t = 0; t < 8; t++) {
            int idx = (tid + t * 256) * 4;
            *(float4*)(Ws + idx) = *(const float4*)(g_wt + k0 * 256 + idx);
        }
        __syncthreads();

#pragma unroll
        for (int kk = 0; kk < BK; kk++) {
            float a[8], b[8];
#pragma unroll
            for (int i = 0; i < 8; i++) a[i] = Xs[(warp * 8 + i) * BK + kk];
            float4 b0 = *(float4*)(Ws + kk * 256 + lane * 8);
            float4 b1 = *(float4*)(Ws + kk * 256 + lane * 8 + 4);
            b[0] = b0.x; b[1] = b0.y; b[2] = b0.z; b[3] = b0.w;
            b[4] = b1.x; b[5] = b1.y; b[6] = b1.z; b[7] = b1.w;
#pragma unroll
            for (int i = 0; i < 8; i++)
#pragma unroll
                for (int j = 0; j < 8; j++) acc[i][j] = fmaf(a[i], b[j], acc[i][j]);
        }
        __syncthreads();
    }

#pragma unroll
    for (int i = 0; i < 8; i++) {
        int r = row0 + warp * 8 + i;
        if (r >= N_NODES) continue;
        float* base = (lane < 16) ? (g_xl + (size_t)r * HID + lane * 8)
                                  : (g_xr + (size_t)r * HID + (lane - 16) * 8);
        *(float4*)base       = make_float4(acc[i][0], acc[i][1], acc[i][2], acc[i][3]);
        *(float4*)(base + 4) = make_float4(acc[i][4], acc[i][5], acc[i][6], acc[i][7]);
    }
}

// ---------------- init accumulators ----------------
__global__ void k_init() {
    int i = blockIdx.x * blockDim.x + threadIdx.x;
    if (i < N_NODES * HID) g_acc[i] = 0.f;
    if (i < N_NODES * HEADS) {
        g_amax[i] = -CUDART_INF_F;
        g_asum[i] = 0.f;
    }
}

// ---------------- per-edge attention logits + segment max ------------------
// one warp per edge; lanes 0-15 head 0, lanes 16-31 head 1 (4 ch each)
__global__ void k_alpha(const int* __restrict__ src, const int* __restrict__ dst,
                        const float* __restrict__ att) {
    int e = (blockIdx.x * blockDim.x + threadIdx.x) >> 5;
    int lane = threadIdx.x & 31;
    if (e >= E_EDGES) return;
    int s = src[e], d = dst[e];
    float4 xl = *(const float4*)(g_xl + (size_t)s * HID + lane * 4);
    float4 xr = *(const float4*)(g_xr + (size_t)d * HID + lane * 4);
    float4 at = *(const float4*)(att + lane * 4);
    float p = lrelu(xl.x + xr.x, ATT_SLOPE) * at.x
            + lrelu(xl.y + xr.y, ATT_SLOPE) * at.y
            + lrelu(xl.z + xr.z, ATT_SLOPE) * at.z
            + lrelu(xl.w + xr.w, ATT_SLOPE) * at.w;
    p += __shfl_xor_sync(0xffffffffu, p, 8);
    p += __shfl_xor_sync(0xffffffffu, p, 4);
    p += __shfl_xor_sync(0xffffffffu, p, 2);
    p += __shfl_xor_sync(0xffffffffu, p, 1);
    if ((lane & 15) == 0) {
        int h = lane >> 4;
        g_alpha[(size_t)e * HEADS + h] = p;
        atomicMaxF(&g_amax[d * HEADS + h], p);
    }
}

// ---------------- exp + segment sum ----------------
__global__ void k_expsum(const int* __restrict__ dst) {
    int i = blockIdx.x * blockDim.x + threadIdx.x;
    if (i >= E_EDGES * HEADS) return;
    int e = i >> 1, h = i & 1;
    int d = dst[e];
    float ex = __expf(g_alpha[i] - g_amax[d * HEADS + h]);
    g_alpha[i] = ex;
    atomicAdd(&g_asum[d * HEADS + h], ex);
}

// ---------------- weighted aggregation (scatter-add) ----------------
__global__ void k_aggregate(const int* __restrict__ src, const int* __restrict__ dst) {
    int e = (blockIdx.x * blockDim.x + threadIdx.x) >> 5;
    int lane = threadIdx.x & 31;
    if (e >= E_EDGES) return;
    int s = src[e], d = dst[e];
    int h = lane >> 4;
    float w = g_alpha[(size_t)e * HEADS + h] / (g_asum[d * HEADS + h] + 1e-16f);
    float4 v = *(const float4*)(g_xl + (size_t)s * HID + lane * 4);
    float* out = g_acc + (size_t)d * HID + lane * 4;
    asm volatile("red.global.add.v4.f32 [%0], {%1,%2,%3,%4};"
                 :: "l"(out), "f"(v.x * w), "f"(v.y * w), "f"(v.z * w), "f"(v.w * w)
                 : "memory");
}

// ---------------- finalize layer 1: h1 = leaky(acc + b, 0.01) -------------
__global__ void k_fin1(const float* __restrict__ b) {
    int i = blockIdx.x * blockDim.x + threadIdx.x;
    if (i >= N_NODES * HID) return;
    g_h1[i] = lrelu(g_acc[i] + b[i & (HID - 1)], OUT_SLOPE);
}

// ---------------- finalize layer 2: out = h1 + acc + b ---------------------
__global__ void k_fin2(const float* __restrict__ b, float* __restrict__ out) {
    int i = blockIdx.x * blockDim.x + threadIdx.x;
    if (i >= N_NODES * HID) return;
    out[i] = g_h1[i] + g_acc[i] + b[i & (HID - 1)];
}

// ---------------- launch ----------------
extern "C" void kernel_launch(void* const* d_in, const int* in_sizes, int n_in,
                              void* d_out, int out_size) {
    const float* x    = (const float*)d_in[0];
    const int*   ei   = (const int*)d_in[1];
    const float* wl1  = (const float*)d_in[2];
    const float* wr1  = (const float*)d_in[3];
    const float* att1 = (const float*)d_in[4];
    const float* b1   = (const float*)d_in[5];
    const float* wl2  = (const float*)d_in[6];
    const float* wr2  = (const float*)d_in[7];
    const float* att2 = (const float*)d_in[8];
    const float* b2   = (const float*)d_in[9];
    float* out = (float*)d_out;

    const int* src = ei;
    const int* dst = ei + E_EDGES;

    void* h1_ptr = nullptr;
    cudaGetSymbolAddress(&h1_ptr, g_h1);

    const int gemm_blocks = (N_NODES + BM - 1) / BM;          // 782
    const int edge_warp_blocks = (E_EDGES + 7) / 8;           // 80000 (8 warps/block)
    const int nh_blocks = (N_NODES * HID + 255) / 256;        // 25000
    const int eh_blocks = (E_EDGES * HEADS + 255) / 256;      // 5000

    // ---- layer 1 ----
    k_transpose<<<(HID * HID + 255) / 256, 256>>>(wl1, wr1);
    k_gemm<<<gemm_blocks, 256>>>(x);
    k_init<<<nh_blocks, 256>>>();
    k_alpha<<<edge_warp_blocks, 256>>>(src, dst, att1);
    k_expsum<<<eh_blocks, 256>>>(dst);
    k_aggregate<<<edge_warp_blocks, 256>>>(src, dst);
    k_fin1<<<nh_blocks, 256>>>(b1);

    // ---- layer 2 ----
    k_transpose<<<(HID * HID + 255) / 256, 256>>>(wl2, wr2);
    k_gemm<<<gemm_blocks, 256>>>((const float*)h1_ptr);
    k_init<<<nh_blocks, 256>>>();
    k_alpha<<<edge_warp_blocks, 256>>>(src, dst, att2);
    k_expsum<<<eh_blocks, 256>>>(dst);
    k_aggregate<<<edge_warp_blocks, 256>>>(src, dst);
    k_fin2<<<nh_blocks, 256>>>(b2, out);
}

// round 2
// speedup vs baseline: 1.5653x; 1.5653x over previous
#include <cuda_runtime.h>
#include <math_constants.h>

#define N_NODES 50000
#define HID     128
#define E_EDGES 640000
#define HEADS   2
#define ATT_SLOPE 0.2f
#define OUT_SLOPE 0.01f

// ---------------- scratch (device globals; no allocation allowed) ----------
__device__ float g_xl[N_NODES * HID];
__device__ float g_xr[N_NODES * HID];
__device__ float g_h1[N_NODES * HID];
__device__ float g_wt[HID * 2 * HID];   // [k][256]: cols 0..127 = W_l, 128..255 = W_r
__device__ int   g_deg[N_NODES];
__device__ int   g_rowptr[N_NODES + 1];
__device__ int   g_cursor[N_NODES];
__device__ int   g_esrc[E_EDGES];       // src node ids grouped by dst

__device__ __forceinline__ float lrelu(float x, float s) {
    return x > 0.f ? x : s * x;
}

// ---------------- CSR build ----------------
__global__ void k_zero_deg() {
    int i = blockIdx.x * blockDim.x + threadIdx.x;
    if (i < N_NODES) g_deg[i] = 0;
}

__global__ void k_hist(const int* __restrict__ dst) {
    int i = blockIdx.x * blockDim.x + threadIdx.x;
    if (i < E_EDGES) atomicAdd(&g_deg[dst[i]], 1);
}

// single-block exclusive scan over 50000 degrees -> rowptr + cursor
__global__ void __launch_bounds__(1024) k_scan() {
    __shared__ int ssum[1024];
    const int t = threadIdx.x;
    const int CH = (N_NODES + 1023) / 1024;   // 49
    const int base = t * CH;
    int s = 0;
    for (int j = 0; j < CH; j++) {
        int idx = base + j;
        if (idx < N_NODES) s += g_deg[idx];
    }
    ssum[t] = s;
    __syncthreads();
    for (int off = 1; off < 1024; off <<= 1) {
        int v = (t >= off) ? ssum[t - off] : 0;
        __syncthreads();
        ssum[t] += v;
        __syncthreads();
    }
    int run = (t == 0) ? 0 : ssum[t - 1];
    for (int j = 0; j < CH; j++) {
        int idx = base + j;
        if (idx < N_NODES) {
            g_rowptr[idx] = run;
            g_cursor[idx] = run;
            run += g_deg[idx];
        }
    }
    if (t == 1023) g_rowptr[N_NODES] = ssum[1023];
}

__global__ void k_scatter(const int* __restrict__ src, const int* __restrict__ dst) {
    int i = blockIdx.x * blockDim.x + threadIdx.x;
    if (i < E_EDGES) {
        int p = atomicAdd(&g_cursor[dst[i]], 1);
        g_esrc[p] = src[i];
    }
}

// ---------------- W transpose: [o][k] -> [k][o || 128+o] -------------------
__global__ void k_transpose(const float* __restrict__ wl, const float* __restrict__ wr) {
    int i = blockIdx.x * blockDim.x + threadIdx.x;
    if (i < HID * HID) {
        int o = i / HID, k = i % HID;
        g_wt[k * 256 + o]       = wl[i];
        g_wt[k * 256 + 128 + o] = wr[i];
    }
}

// ---------------- fused GEMM: [n,0:128] -> g_xl, [n,128:256] -> g_xr -------
#define BM 64
#define BK 32
__global__ void __launch_bounds__(256, 2) k_gemm(const float* __restrict__ X) {
    __shared__ float Xs[BM * BK];
    __shared__ float Ws[BK * 256];
    const int tid  = threadIdx.x;
    const int warp = tid >> 5;
    const int lane = tid & 31;
    const int row0 = blockIdx.x * BM;

    float acc[8][8];
#pragma unroll
    for (int i = 0; i < 8; i++)
#pragma unroll
        for (int j = 0; j < 8; j++) acc[i][j] = 0.f;

    for (int k0 = 0; k0 < HID; k0 += BK) {
#pragma unroll
        for (int t = 0; t < 2; t++) {
            int idx = (tid + t * 256) * 4;
            int r = idx >> 5, kk = idx & 31;
            int rg = row0 + r;
            float4 v = make_float4(0.f, 0.f, 0.f, 0.f);
            if (rg < N_NODES)
                v = *(const float4*)(X + (size_t)rg * HID + k0 + kk);
            *(float4*)(Xs + r * BK + kk) = v;
        }
#pragma unroll
        for (int t = 0; t < 8; t++) {
            int idx = (tid + t * 256) * 4;
            *(float4*)(Ws + idx) = *(const float4*)(g_wt + k0 * 256 + idx);
        }
        __syncthreads();

#pragma unroll
        for (int kk = 0; kk < BK; kk++) {
            float a[8], b[8];
#pragma unroll
            for (int i = 0; i < 8; i++) a[i] = Xs[(warp * 8 + i) * BK + kk];
            float4 b0 = *(float4*)(Ws + kk * 256 + lane * 8);
            float4 b1 = *(float4*)(Ws + kk * 256 + lane * 8 + 4);
            b[0] = b0.x; b[1] = b0.y; b[2] = b0.z; b[3] = b0.w;
            b[4] = b1.x; b[5] = b1.y; b[6] = b1.z; b[7] = b1.w;
#pragma unroll
            for (int i = 0; i < 8; i++)
#pragma unroll
                for (int j = 0; j < 8; j++) acc[i][j] = fmaf(a[i], b[j], acc[i][j]);
        }
        __syncthreads();
    }

#pragma unroll
    for (int i = 0; i < 8; i++) {
        int r = row0 + warp * 8 + i;
        if (r >= N_NODES) continue;
        float* base = (lane < 16) ? (g_xl + (size_t)r * HID + lane * 8)
                                  : (g_xr + (size_t)r * HID + (lane - 16) * 8);
        *(float4*)base       = make_float4(acc[i][0], acc[i][1], acc[i][2], acc[i][3]);
        *(float4*)(base + 4) = make_float4(acc[i][4], acc[i][5], acc[i][6], acc[i][7]);
    }
}

// ---------------- fused per-node attention + softmax + aggregate -----------
// One warp per dst node. Lane l owns channels [4l, 4l+4); lanes 0-15 = head 0,
// lanes 16-31 = head 1. Single pass (no max subtraction — logits are O(1)):
//   acc += exp(alpha) * x_l[src];  sum += exp(alpha);  out = acc/sum + b.
template <int LAYER>
__global__ void k_node(const float* __restrict__ att, const float* __restrict__ b,
                       float* __restrict__ outbuf) {
    const int n    = (blockIdx.x * blockDim.x + threadIdx.x) >> 5;
    const int lane = threadIdx.x & 31;
    if (n >= N_NODES) return;

    const int beg = g_rowptr[n];
    const int end = g_rowptr[n + 1];

    const float4 xr = *(const float4*)(g_xr + (size_t)n * HID + lane * 4);
    const float4 at = *(const float4*)(att + lane * 4);

    float4 acc = make_float4(0.f, 0.f, 0.f, 0.f);
    float  sum = 0.f;

    for (int i0 = beg; i0 < end; i0 += 32) {
        const int cnt = min(32, end - i0);
        int sid = (lane < cnt) ? g_esrc[i0 + lane] : 0;
        for (int j = 0; j < cnt; j++) {
            const int s = __shfl_sync(0xffffffffu, sid, j);
            const float4 xl = *(const float4*)(g_xl + (size_t)s * HID + lane * 4);
            float p = lrelu(xl.x + xr.x, ATT_SLOPE) * at.x
                    + lrelu(xl.y + xr.y, ATT_SLOPE) * at.y
                    + lrelu(xl.z + xr.z, ATT_SLOPE) * at.z
                    + lrelu(xl.w + xr.w, ATT_SLOPE) * at.w;
            // reduce within each 16-lane half (per head)
            p += __shfl_xor_sync(0xffffffffu, p, 8);
            p += __shfl_xor_sync(0xffffffffu, p, 4);
            p += __shfl_xor_sync(0xffffffffu, p, 2);
            p += __shfl_xor_sync(0xffffffffu, p, 1);
            const float ex = __expf(p);
            sum += ex;
            acc.x = fmaf(ex, xl.x, acc.x);
            acc.y = fmaf(ex, xl.y, acc.y);
            acc.z = fmaf(ex, xl.z, acc.z);
            acc.w = fmaf(ex, xl.w, acc.w);
        }
    }

    const float inv = 1.f / (sum + 1e-16f);
    const float4 bb = *(const float4*)(b + lane * 4);
    float4 o;
    o.x = fmaf(acc.x, inv, bb.x);
    o.y = fmaf(acc.y, inv, bb.y);
    o.z = fmaf(acc.z, inv, bb.z);
    o.w = fmaf(acc.w, inv, bb.w);

    float* dstp = outbuf + (size_t)n * HID + lane * 4;
    if (LAYER == 1) {
        o.x = lrelu(o.x, OUT_SLOPE);
        o.y = lrelu(o.y, OUT_SLOPE);
        o.z = lrelu(o.z, OUT_SLOPE);
        o.w = lrelu(o.w, OUT_SLOPE);
        *(float4*)dstp = o;
    } else {
        const float4 h = *(const float4*)(g_h1 + (size_t)n * HID + lane * 4);
        o.x += h.x; o.y += h.y; o.z += h.z; o.w += h.w;
        *(float4*)dstp = o;
    }
}

// ---------------- launch ----------------
extern "C" void kernel_launch(void* const* d_in, const int* in_sizes, int n_in,
                              void* d_out, int out_size) {
    const float* x    = (const float*)d_in[0];
    const int*   ei   = (const int*)d_in[1];
    const float* wl1  = (const float*)d_in[2];
    const float* wr1  = (const float*)d_in[3];
    const float* att1 = (const float*)d_in[4];
    const float* b1   = (const float*)d_in[5];
    const float* wl2  = (const float*)d_in[6];
    const float* wr2  = (const float*)d_in[7];
    const float* att2 = (const float*)d_in[8];
    const float* b2   = (const float*)d_in[9];
    float* out = (float*)d_out;

    const int* src = ei;
    const int* dst = ei + E_EDGES;

    void* h1_ptr = nullptr;
    cudaGetSymbolAddress(&h1_ptr, g_h1);

    const int gemm_blocks = (N_NODES + BM - 1) / BM;       // 782
    const int node_blocks = (N_NODES * 32 + 255) / 256;    // 6250 (1 warp/node)
    const int e_blocks    = (E_EDGES + 255) / 256;
    const int n_blocks    = (N_NODES + 255) / 256;

    // ---- CSR build (once; shared by both layers) ----
    k_zero_deg<<<n_blocks, 256>>>();
    k_hist<<<e_blocks, 256>>>(dst);
    k_scan<<<1, 1024>>>();
    k_scatter<<<e_blocks, 256>>>(src, dst);

    // ---- layer 1 ----
    k_transpose<<<(HID * HID + 255) / 256, 256>>>(wl1, wr1);
    k_gemm<<<gemm_blocks, 256>>>(x);
    k_node<1><<<node_blocks, 256>>>(att1, b1, (float*)h1_ptr);

    // ---- layer 2 ----
    k_transpose<<<(HID * HID + 255) / 256, 256>>>(wl2, wr2);
    k_gemm<<<gemm_blocks, 256>>>((const float*)h1_ptr);
    k_node<2><<<node_blocks, 256>>>(att2, b2, out);
}

// round 4
// speedup vs baseline: 1.5969x; 1.0202x over previous
#include <cuda_runtime.h>
#include <cuda_bf16.h>
#include <math_constants.h>
#include <cstdint>

#define N_NODES 50000
#define HID     128
#define E_EDGES 640000
#define ATT_SLOPE 0.2f
#define OUT_SLOPE 0.01f

// ---------------- scratch (device globals; no allocation allowed) ----------
__device__ float g_xl[N_NODES * HID];
__device__ float g_xr[N_NODES * HID];
__device__ float g_h1[N_NODES * HID];
__device__ int   g_deg[N_NODES];
__device__ int   g_rowptr[N_NODES + 1];
__device__ int   g_cursor[N_NODES];
__device__ int   g_esrc[E_EDGES];

__device__ __forceinline__ float lrelu(float x, float s) { return x > 0.f ? x : s * x; }

__device__ __forceinline__ uint32_t s2u(const void* p) {
    uint32_t a;
    asm("{ .reg .u64 t; cvta.to.shared.u64 t, %1; cvt.u32.u64 %0, t; }" : "=r"(a) : "l"(p));
    return a;
}

// ---------------- CSR build ----------------
__global__ void k_zero_deg() {
    int i = blockIdx.x * blockDim.x + threadIdx.x;
    if (i < N_NODES) g_deg[i] = 0;
}
__global__ void k_hist(const int* __restrict__ dst) {
    int i = blockIdx.x * blockDim.x + threadIdx.x;
    if (i < E_EDGES) atomicAdd(&g_deg[dst[i]], 1);
}
__global__ void __launch_bounds__(1024) k_scan() {
    __shared__ int ssum[1024];
    const int t = threadIdx.x;
    const int CH = (N_NODES + 1023) / 1024;
    const int base = t * CH;
    int s = 0;
    for (int j = 0; j < CH; j++) { int idx = base + j; if (idx < N_NODES) s += g_deg[idx]; }
    ssum[t] = s;
    __syncthreads();
    for (int off = 1; off < 1024; off <<= 1) {
        int v = (t >= off) ? ssum[t - off] : 0;
        __syncthreads();
        ssum[t] += v;
        __syncthreads();
    }
    int run = (t == 0) ? 0 : ssum[t - 1];
    for (int j = 0; j < CH; j++) {
        int idx = base + j;
        if (idx < N_NODES) { g_rowptr[idx] = run; g_cursor[idx] = run; run += g_deg[idx]; }
    }
    if (t == 1023) g_rowptr[N_NODES] = ssum[1023];
}
__global__ void k_scatter(const int* __restrict__ src, const int* __restrict__ dst) {
    int i = blockIdx.x * blockDim.x + threadIdx.x;
    if (i < E_EDGES) {
        int p = atomicAdd(&g_cursor[dst[i]], 1);
        g_esrc[p] = src[i];
    }
}

// ---------------- split-bf16 HMMA GEMM --------------------------------------
// One CTA: 128 rows x 256 cols, K=128.  D = Xhi*Whi + Xhi*Wlo + Xlo*Whi.
// SMEM rows padded to 136 bf16 (272 B) => ldmatrix conflict-free (4-bank/row
// stagger covers all 32 banks across the 8 rows of each 8x8 matrix).
#define LDP   136                      // padded row length (bf16 elems)
#define LDPU  68                       // padded row length (u32)
#define SMEM_AHI 0
#define SMEM_ALO (SMEM_AHI + 128 * LDP * 2)       //  34816
#define SMEM_BHI (SMEM_ALO + 128 * LDP * 2)       //  69632
#define SMEM_BLO (SMEM_BHI + 256 * LDP * 2)       // 139264
#define SMEM_TOT (SMEM_BLO + 256 * LDP * 2)       // 208896

__device__ __forceinline__ void ldsm4(uint32_t& r0, uint32_t& r1, uint32_t& r2,
                                      uint32_t& r3, uint32_t addr) {
    asm volatile("ldmatrix.sync.aligned.m8n8.x4.shared.b16 {%0,%1,%2,%3}, [%4];"
                 : "=r"(r0), "=r"(r1), "=r"(r2), "=r"(r3) : "r"(addr));
}
__device__ __forceinline__ void mma16816(float* c, const uint32_t* a, const uint32_t* b) {
    asm volatile(
        "mma.sync.aligned.m16n8k16.row.col.f32.bf16.bf16.f32 "
        "{%0,%1,%2,%3}, {%4,%5,%6,%7}, {%8,%9}, {%0,%1,%2,%3};"
        : "+f"(c[0]), "+f"(c[1]), "+f"(c[2]), "+f"(c[3])
        : "r"(a[0]), "r"(a[1]), "r"(a[2]), "r"(a[3]), "r"(b[0]), "r"(b[1]));
}
__device__ __forceinline__ uint32_t pack_hi(float x, float y) {
    __nv_bfloat16 hx = __float2bfloat16(x), hy = __float2bfloat16(y);
    return ((uint32_t)__bfloat16_as_ushort(hy) << 16) | __bfloat16_as_ushort(hx);
}
__device__ __forceinline__ uint32_t pack_lo(float x, float y) {
    __nv_bfloat16 hx = __float2bfloat16(x), hy = __float2bfloat16(y);
    __nv_bfloat16 lx = __float2bfloat16(x - __bfloat162float(hx));
    __nv_bfloat16 ly = __float2bfloat16(y - __bfloat162float(hy));
    return ((uint32_t)__bfloat16_as_ushort(ly) << 16) | __bfloat16_as_ushort(lx);
}

__global__ void __launch_bounds__(512, 1)
k_gemm_tc(const float* __restrict__ X,
          const float* __restrict__ wl, const float* __restrict__ wr) {
    extern __shared__ char smem[];
    const uint32_t sb = s2u(smem);
    const int tid  = threadIdx.x;
    const int warp = tid >> 5;
    const int lane = tid & 31;
    uint32_t* su = (uint32_t*)smem;

    // ---- stage W: [n=256][k=128] fp32 -> bf16 hi/lo, padded SMEM ----
    for (int i = tid; i < 256 * 64; i += 512) {        // 64 float2-pairs per row
        int n = i >> 6, p = i & 63;
        const float* wp = ((n < 128) ? wl : wr) + (size_t)(n & 127) * 128 + p * 2;
        float2 v = *(const float2*)wp;
        su[(SMEM_BHI >> 2) + n * LDPU + p] = pack_hi(v.x, v.y);
        su[(SMEM_BLO >> 2) + n * LDPU + p] = pack_lo(v.x, v.y);
    }
    // ---- stage X tile: 128 rows fp32 -> bf16 hi/lo ----
    for (int i = tid; i < 128 * 64; i += 512) {
        int r = i >> 6, p = i & 63;
        long grow = (long)blockIdx.x * 128 + r;
        float2 v = make_float2(0.f, 0.f);
        if (grow < N_NODES) v = *(const float2*)(X + grow * HID + p * 2);
        su[(SMEM_AHI >> 2) + r * LDPU + p] = pack_hi(v.x, v.y);
        su[(SMEM_ALO >> 2) + r * LDPU + p] = pack_lo(v.x, v.y);
    }
    __syncthreads();

    // ---- compute: warp tile 32x64 (warps: 4 in M x 4 in N) ----
    const int wm = (warp >> 2) * 32;
    const int wn = (warp & 3) * 64;
    float c[2][8][4];
#pragma unroll
    for (int mi = 0; mi < 2; mi++)
#pragma unroll
        for (int ni = 0; ni < 8; ni++)
#pragma unroll
            for (int q = 0; q < 4; q++) c[mi][ni][q] = 0.f;

    // per-lane ldmatrix address components
    const uint32_t aRowOff = (uint32_t)((wm + (lane & 15)) * LDP + ((lane >> 4) << 3)) << 1;
    const uint32_t bRowOff = (uint32_t)((wn + ((lane >> 4) << 3) + (lane & 7)) * LDP
                                        + (((lane >> 3) & 1) << 3)) << 1;

#pragma unroll
    for (int term = 0; term < 3; term++) {
        const uint32_t Ab = sb + (term == 2 ? SMEM_ALO : SMEM_AHI) + aRowOff;
        const uint32_t Bb = sb + (term == 1 ? SMEM_BLO : SMEM_BHI) + bRowOff;
#pragma unroll
        for (int k0 = 0; k0 < 128; k0 += 16) {
            uint32_t a[2][4];
            ldsm4(a[0][0], a[0][1], a[0][2], a[0][3], Ab + (k0 << 1));
            ldsm4(a[1][0], a[1][1], a[1][2], a[1][3], Ab + ((16 * LDP) << 1) + (k0 << 1));
            uint32_t b[8][2];
#pragma unroll
            for (int nq = 0; nq < 4; nq++) {
                uint32_t r0, r1, r2, r3;
                ldsm4(r0, r1, r2, r3, Bb + ((nq * 16 * LDP) << 1) + (k0 << 1));
                b[nq * 2][0] = r0; b[nq * 2][1] = r1;
                b[nq * 2 + 1][0] = r2; b[nq * 2 + 1][1] = r3;
            }
#pragma unroll
            for (int mi = 0; mi < 2; mi++)
#pragma unroll
                for (int ni = 0; ni < 8; ni++)
                    mma16816(c[mi][ni], a[mi], b[ni]);
        }
    }

    // ---- epilogue: cols 0..127 -> g_xl, 128..255 -> g_xr ----
    float* buf = (wn < 128) ? g_xl : g_xr;
    const int colbase = (wn & 127) + (lane & 3) * 2;
#pragma unroll
    for (int mi = 0; mi < 2; mi++) {
#pragma unroll
        for (int half = 0; half < 2; half++) {
            long row = (long)blockIdx.x * 128 + wm + mi * 16 + (lane >> 2) + half * 8;
            if (row >= N_NODES) continue;
            float* rp = buf + row * HID + colbase;
#pragma unroll
            for (int ni = 0; ni < 8; ni++) {
                float2 v = make_float2(c[mi][ni][half * 2], c[mi][ni][half * 2 + 1]);
                *(float2*)(rp + ni * 8) = v;
            }
        }
    }
}

// ---------------- fused per-node attention + softmax + aggregate -----------
template <int LAYER>
__global__ void k_node(const float* __restrict__ att, const float* __restrict__ b,
                       float* __restrict__ outbuf) {
    const int n    = (blockIdx.x * blockDim.x + threadIdx.x) >> 5;
    const int lane = threadIdx.x & 31;
    if (n >= N_NODES) return;

    const int beg = g_rowptr[n];
    const int end = g_rowptr[n + 1];

    const float4 xr = *(const float4*)(g_xr + (size_t)n * HID + lane * 4);
    const float4 at = *(const float4*)(att + lane * 4);

    float4 acc = make_float4(0.f, 0.f, 0.f, 0.f);
    float  sum = 0.f;

    for (int i0 = beg; i0 < end; i0 += 32) {
        const int cnt = min(32, end - i0);
        int sid = (lane < cnt) ? g_esrc[i0 + lane] : 0;
        for (int j = 0; j < cnt; j++) {
            const int s = __shfl_sync(0xffffffffu, sid, j);
            const float4 xl = *(const float4*)(g_xl + (size_t)s * HID + lane * 4);
            float p = lrelu(xl.x + xr.x, ATT_SLOPE) * at.x
                    + lrelu(xl.y + xr.y, ATT_SLOPE) * at.y
                    + lrelu(xl.z + xr.z, ATT_SLOPE) * at.z
                    + lrelu(xl.w + xr.w, ATT_SLOPE) * at.w;
            p += __shfl_xor_sync(0xffffffffu, p, 8);
            p += __shfl_xor_sync(0xffffffffu, p, 4);
            p += __shfl_xor_sync(0xffffffffu, p, 2);
            p += __shfl_xor_sync(0xffffffffu, p, 1);
            const float ex = __expf(p);
            sum += ex;
            acc.x = fmaf(ex, xl.x, acc.x);
            acc.y = fmaf(ex, xl.y, acc.y);
            acc.z = fmaf(ex, xl.z, acc.z);
            acc.w = fmaf(ex, xl.w, acc.w);
        }
    }

    const float inv = 1.f / (sum + 1e-16f);
    const float4 bb = *(const float4*)(b + lane * 4);
    float4 o;
    o.x = fmaf(acc.x, inv, bb.x);
    o.y = fmaf(acc.y, inv, bb.y);
    o.z = fmaf(acc.z, inv, bb.z);
    o.w = fmaf(acc.w, inv, bb.w);

    float* dstp = outbuf + (size_t)n * HID + lane * 4;
    if (LAYER == 1) {
        o.x = lrelu(o.x, OUT_SLOPE);
        o.y = lrelu(o.y, OUT_SLOPE);
        o.z = lrelu(o.z, OUT_SLOPE);
        o.w = lrelu(o.w, OUT_SLOPE);
        *(float4*)dstp = o;
    } else {
        const float4 h = *(const float4*)(g_h1 + (size_t)n * HID + lane * 4);
        o.x += h.x; o.y += h.y; o.z += h.z; o.w += h.w;
        *(float4*)dstp = o;
    }
}

// ---------------- launch ----------------
extern "C" void kernel_launch(void* const* d_in, const int* in_sizes, int n_in,
                              void* d_out, int out_size) {
    const float* x    = (const float*)d_in[0];
    const int*   ei   = (const int*)d_in[1];
    const float* wl1  = (const float*)d_in[2];
    const float* wr1  = (const float*)d_in[3];
    const float* att1 = (const float*)d_in[4];
    const float* b1   = (const float*)d_in[5];
    const float* wl2  = (const float*)d_in[6];
    const float* wr2  = (const float*)d_in[7];
    const float* att2 = (const float*)d_in[8];
    const float* b2   = (const float*)d_in[9];
    float* out = (float*)d_out;

    const int* src = ei;
    const int* dst = ei + E_EDGES;

    void* h1_ptr = nullptr;
    cudaGetSymbolAddress(&h1_ptr, g_h1);

    cudaFuncSetAttribute(k_gemm_tc, cudaFuncAttributeMaxDynamicSharedMemorySize, SMEM_TOT);

    const int gemm_blocks = (N_NODES + 127) / 128;         // 391
    const int node_blocks = (N_NODES * 32 + 255) / 256;    // 6250
    const int e_blocks    = (E_EDGES + 255) / 256;
    const int n_blocks    = (N_NODES + 255) / 256;

    // ---- CSR build (once) ----
    k_zero_deg<<<n_blocks, 256>>>();
    k_hist<<<e_blocks, 256>>>(dst);
    k_scan<<<1, 1024>>>();
    k_scatter<<<e_blocks, 256>>>(src, dst);

    // ---- layer 1 ----
    k_gemm_tc<<<gemm_blocks, 512, SMEM_TOT>>>(x, wl1, wr1);
    k_node<1><<<node_blocks, 256>>>(att1, b1, (float*)h1_ptr);

    // ---- layer 2 ----
    k_gemm_tc<<<gemm_blocks, 512, SMEM_TOT>>>((const float*)h1_ptr, wl2, wr2);
    k_node<2><<<node_blocks, 256>>>(att2, b2, out);
}